// round 1
// baseline (speedup 1.0000x reference)
#include <cuda_runtime.h>
#include <cstdint>
#include <math.h>

#define T_STEPS 512
#define BATCH   256
#define DIN     256
#define HDIM    128
#define G4      512   // 4*H

// Scratch (device globals — no allocations allowed in kernel_launch)
__device__ float XG[(size_t)T_STEPS * BATCH * G4];   // 268 MB precomputed input gates
__device__ float HFIN[BATCH * HDIM];                 // final hidden state

// ---------- math helpers (fast-math-safe: built on expf only) ----------
__device__ __forceinline__ float sigmoid_(float x) { return 1.0f / (1.0f + expf(-x)); }
__device__ __forceinline__ float tanh_(float x)    { return 1.0f - 2.0f / (expf(2.0f * x) + 1.0f); }

// =====================================================================
// Kernel 1: XG[m][n] = sum_k X[m][k] * W_ih[n][k] + b_ih[n] + b_hh[n]
//           M = T*B = 131072, N = 512, K = 256
// Tiling: BM=128, BN=128, BK=16, 256 threads, 8x8 register tile.
// =====================================================================
#define BM 128
#define BN 128
#define BK 16

__global__ __launch_bounds__(256) void xg_gemm(const float* __restrict__ X,
                                               const float* __restrict__ W,
                                               const float* __restrict__ b_ih,
                                               const float* __restrict__ b_hh)
{
    __shared__ float Xs[BK][BM];
    __shared__ float Ws[BK][BN];

    const int tid = threadIdx.x;
    const int m0 = blockIdx.x * BM;
    const int n0 = blockIdx.y * BN;
    const int tx = tid & 15;
    const int ty = tid >> 4;

    float acc[8][8];
#pragma unroll
    for (int i = 0; i < 8; i++)
#pragma unroll
        for (int j = 0; j < 8; j++) acc[i][j] = 0.0f;

    // loader: each thread loads 8 contiguous k-floats of one row (2 x float4)
    const int lr = tid >> 1;         // row within tile 0..127
    const int lk = (tid & 1) * 8;    // k offset 0 or 8

    for (int kt = 0; kt < DIN; kt += BK) {
        const float4* xg = (const float4*)(X + (size_t)(m0 + lr) * DIN + kt + lk);
        float4 a0 = xg[0];
        float4 a1 = xg[1];
        Xs[lk + 0][lr] = a0.x; Xs[lk + 1][lr] = a0.y; Xs[lk + 2][lr] = a0.z; Xs[lk + 3][lr] = a0.w;
        Xs[lk + 4][lr] = a1.x; Xs[lk + 5][lr] = a1.y; Xs[lk + 6][lr] = a1.z; Xs[lk + 7][lr] = a1.w;

        const float4* wg = (const float4*)(W + (size_t)(n0 + lr) * DIN + kt + lk);
        float4 c0 = wg[0];
        float4 c1 = wg[1];
        Ws[lk + 0][lr] = c0.x; Ws[lk + 1][lr] = c0.y; Ws[lk + 2][lr] = c0.z; Ws[lk + 3][lr] = c0.w;
        Ws[lk + 4][lr] = c1.x; Ws[lk + 5][lr] = c1.y; Ws[lk + 6][lr] = c1.z; Ws[lk + 7][lr] = c1.w;

        __syncthreads();

#pragma unroll
        for (int k = 0; k < BK; k++) {
            float4 xv0 = *(const float4*)&Xs[k][ty * 8];
            float4 xv1 = *(const float4*)&Xs[k][ty * 8 + 4];
            float4 wv0 = *(const float4*)&Ws[k][tx * 8];
            float4 wv1 = *(const float4*)&Ws[k][tx * 8 + 4];
            float xr[8] = {xv0.x, xv0.y, xv0.z, xv0.w, xv1.x, xv1.y, xv1.z, xv1.w};
            float wr[8] = {wv0.x, wv0.y, wv0.z, wv0.w, wv1.x, wv1.y, wv1.z, wv1.w};
#pragma unroll
            for (int i = 0; i < 8; i++)
#pragma unroll
                for (int j = 0; j < 8; j++) acc[i][j] += xr[i] * wr[j];
        }
        __syncthreads();
    }

    // epilogue: add biases, store
    float bias[8];
#pragma unroll
    for (int j = 0; j < 8; j++) {
        int n = n0 + tx * 8 + j;
        bias[j] = b_ih[n] + b_hh[n];
    }
#pragma unroll
    for (int i = 0; i < 8; i++) {
        size_t m = (size_t)m0 + ty * 8 + i;
        float4* crow = (float4*)(XG + m * G4 + n0 + tx * 8);
        float4 v0, v1;
        v0.x = acc[i][0] + bias[0]; v0.y = acc[i][1] + bias[1];
        v0.z = acc[i][2] + bias[2]; v0.w = acc[i][3] + bias[3];
        v1.x = acc[i][4] + bias[4]; v1.y = acc[i][5] + bias[5];
        v1.z = acc[i][6] + bias[6]; v1.w = acc[i][7] + bias[7];
        crow[0] = v0;
        crow[1] = v1;
    }
}

// =====================================================================
// Kernel 2: recurrence. Cluster of 2 CTAs handles 4 batch rows.
//  - CTA r (r=0,1) owns h/c columns [64r, 64r+64) and holds, in smem,
//    W_hh rows {g*128 + 64r + c : g in 0..3, c in 0..63}  (256x128 fp32 = 128 KB),
//    stored k-major: Wsm[k][jl], jl = g*64 + c.
//  - Full h (128 cols x 4 batches) lives in smem, double buffered,
//    transposed hsT[buf][k][b] for broadcast-friendly float4 loads.
//  - Each step: partial-K-split GEMM (4-way), smem reduce, activations,
//    write own h-half locally + to peer via DSMEM, cluster arrive/wait.
// 256 threads. GEMM role: (kc = tid>>6, g = tid&63) -> 4 j-rows x 4 batches
// x 32 k. Activation role: (b = tid>>6, col = tid&63) owns one (b,col) cell
// with c persistent in a register.
// =====================================================================
__global__ void __cluster_dims__(2, 1, 1) __launch_bounds__(256)
lstm_rec(const float* __restrict__ h0,
         const float* __restrict__ c0,
         const float* __restrict__ W_hh)
{
    extern __shared__ float sm[];
    float* Wsm = sm;                     // [128][256]  (k-major)   32768 floats
    float* hsT = sm + 32768;             // [2][128][4]              1024 floats
    float* Gsm = sm + 32768 + 1024;      // [4 kc][4 b][256 j]       4096 floats

    const int tid  = threadIdx.x;
    const int r    = blockIdx.x & 1;     // cluster rank (cluster dims (2,1,1))
    const int pair = blockIdx.x >> 1;
    const int b0   = pair * 4;
    const int peer = r ^ 1;

    // ---- load W half (each thread owns one local row j = tid) ----
    {
        const int j = tid;                       // 0..255
        const int gate = j >> 6;
        const int col  = j & 63;
        const int jg = gate * 128 + r * 64 + col;
        const float4* wrow = (const float4*)(W_hh + (size_t)jg * HDIM);
#pragma unroll
        for (int kk = 0; kk < 32; kk++) {
            float4 v = wrow[kk];
            int k = kk * 4;
            Wsm[(k + 0) * 256 + j] = v.x;
            Wsm[(k + 1) * 256 + j] = v.y;
            Wsm[(k + 2) * 256 + j] = v.z;
            Wsm[(k + 3) * 256 + j] = v.w;
        }
    }
    // ---- load full h0 into buffer 0 (transposed) ----
    for (int idx = tid; idx < 512; idx += 256) {
        int b = idx & 3, k = idx >> 2;
        hsT[k * 4 + b] = h0[(size_t)(b0 + b) * HDIM + k];
    }

    // activation-role identity
    const int ab   = tid >> 6;    // batch 0..3
    const int acol = tid & 63;    // own column 0..63
    const int kcol = r * 64 + acol;
    float cst = c0[(size_t)(b0 + ab) * HDIM + kcol];
    float hout = 0.0f;

    // GEMM-role identity
    const int kc = tid >> 6;
    const int g  = tid & 63;

    const uint32_t hsT_u32 = (uint32_t)__cvta_generic_to_shared(hsT);

    __syncthreads();

    const float* xg_base = XG + (size_t)(b0 + ab) * G4 + kcol;

    for (int t = 0; t < T_STEPS; t++) {
        const int pbuf = t & 1;
        const int nbuf = pbuf ^ 1;

        // prefetch this step's input-gate contributions (latency hidden by GEMM)
        const float* xg = xg_base + (size_t)t * BATCH * G4;
        float xgv0 = xg[0];
        float xgv1 = xg[128];
        float xgv2 = xg[256];
        float xgv3 = xg[384];

        // ---- partial GEMM: this thread does j rows [4g,4g+4) x batches 0..3
        //      over k in [32*kc, 32*kc+32) ----
        float4 a0 = {0.f, 0.f, 0.f, 0.f}, a1 = a0, a2 = a0, a3 = a0;
        const float* hbase = hsT + pbuf * 512 + kc * 32 * 4;
        const float* wbase = Wsm + kc * 32 * 256 + 4 * g;
#pragma unroll
        for (int kk = 0; kk < 32; kk++) {
            float4 w = *(const float4*)(wbase + kk * 256);
            float4 h = *(const float4*)(hbase + kk * 4);
            a0.x += w.x * h.x; a0.y += w.y * h.x; a0.z += w.z * h.x; a0.w += w.w * h.x;
            a1.x += w.x * h.y; a1.y += w.y * h.y; a1.z += w.z * h.y; a1.w += w.w * h.y;
            a2.x += w.x * h.z; a2.y += w.y * h.z; a2.z += w.z * h.z; a2.w += w.w * h.z;
            a3.x += w.x * h.w; a3.y += w.y * h.w; a3.z += w.z * h.w; a3.w += w.w * h.w;
        }
        ((float4*)(Gsm + kc * 1024 + 0 * 256))[g] = a0;
        ((float4*)(Gsm + kc * 1024 + 1 * 256))[g] = a1;
        ((float4*)(Gsm + kc * 1024 + 2 * 256))[g] = a2;
        ((float4*)(Gsm + kc * 1024 + 3 * 256))[g] = a3;

        __syncthreads();

        // ---- activation for own cell (ab, acol) ----
        const float* Gb = Gsm + ab * 256;
        float p0 = xgv0 + Gb[0 * 1024 + acol]        + Gb[1 * 1024 + acol]        + Gb[2 * 1024 + acol]        + Gb[3 * 1024 + acol];
        float p1 = xgv1 + Gb[0 * 1024 + 64 + acol]   + Gb[1 * 1024 + 64 + acol]   + Gb[2 * 1024 + 64 + acol]   + Gb[3 * 1024 + 64 + acol];
        float p2 = xgv2 + Gb[0 * 1024 + 128 + acol]  + Gb[1 * 1024 + 128 + acol]  + Gb[2 * 1024 + 128 + acol]  + Gb[3 * 1024 + 128 + acol];
        float p3 = xgv3 + Gb[0 * 1024 + 192 + acol]  + Gb[1 * 1024 + 192 + acol]  + Gb[2 * 1024 + 192 + acol]  + Gb[3 * 1024 + 192 + acol];

        float ig = sigmoid_(p0);
        float fg = sigmoid_(p1);
        float gg = tanh_(p2);
        float og = sigmoid_(p3);
        cst  = fg * cst + ig * gg;
        hout = og * tanh_(cst);

        // ---- publish new h-half: local buffer + peer buffer (DSMEM) ----
        const int off = nbuf * 512 + kcol * 4 + ab;
        hsT[off] = hout;
        uint32_t rem;
        asm volatile("mapa.shared::cluster.u32 %0, %1, %2;"
                     : "=r"(rem) : "r"(hsT_u32 + off * 4), "r"(peer));
        asm volatile("st.shared::cluster.f32 [%0], %1;" :: "r"(rem), "f"(hout) : "memory");

        // cluster barrier (release on arrive / acquire on wait); also acts as
        // the intra-CTA barrier protecting Gsm reuse.
        asm volatile("barrier.cluster.arrive.aligned;" ::: "memory");
        asm volatile("barrier.cluster.wait.aligned;" ::: "memory");
    }

    // final h for this (b, col)
    HFIN[(size_t)(b0 + ab) * HDIM + kcol] = hout;
}

// =====================================================================
// Kernel 3: out[b] = HFIN[b,:] . fc_w + fc_b
// =====================================================================
__global__ __launch_bounds__(256) void fc_head(const float* __restrict__ fcw,
                                               const float* __restrict__ fcb,
                                               float* __restrict__ out)
{
    const int b = threadIdx.x;
    const float4* hr = (const float4*)(HFIN + (size_t)b * HDIM);
    const float4* w4 = (const float4*)fcw;
    float s = 0.0f;
#pragma unroll
    for (int k = 0; k < HDIM / 4; k++) {
        float4 h = hr[k];
        float4 w = w4[k];
        s += h.x * w.x + h.y * w.y + h.z * w.z + h.w * w.w;
    }
    out[b] = s + fcb[0];
}

// =====================================================================
extern "C" void kernel_launch(void* const* d_in, const int* in_sizes, int n_in,
                              void* d_out, int out_size)
{
    const float* x    = (const float*)d_in[0];
    const float* h0   = (const float*)d_in[1];
    const float* c0   = (const float*)d_in[2];
    const float* W_ih = (const float*)d_in[3];
    const float* W_hh = (const float*)d_in[4];
    const float* b_ih = (const float*)d_in[5];
    const float* b_hh = (const float*)d_in[6];
    const float* fc_w = (const float*)d_in[7];
    const float* fc_b = (const float*)d_in[8];
    float* out = (float*)d_out;

    (void)in_sizes; (void)n_in; (void)out_size;

    // 1) big input-projection GEMM
    xg_gemm<<<dim3(131072 / BM, G4 / BN), 256>>>(x, W_ih, b_ih, b_hh);

    // 2) recurrence: 64 cluster-pairs x 2 CTAs, 151552 B dynamic smem each
    const int rec_smem = (32768 + 1024 + 4096) * (int)sizeof(float);
    cudaFuncSetAttribute(lstm_rec, cudaFuncAttributeMaxDynamicSharedMemorySize, rec_smem);
    lstm_rec<<<128, 256, rec_smem>>>(h0, c0, W_hh);

    // 3) FC head
    fc_head<<<1, 256>>>(fc_w, fc_b, out);
}

// round 4
// speedup vs baseline: 1.2770x; 1.2770x over previous
#include <cuda_runtime.h>
#include <cuda_bf16.h>
#include <cstdint>
#include <math.h>

#define T_STEPS 512
#define BATCH   256
#define DIN     256
#define HDIM    128
#define G4      512   // 4*H

// ---------------- device-global scratch (no allocs allowed) ----------------
__device__ __align__(16) float XG[(size_t)T_STEPS * BATCH * G4];   // precomputed input gates
__device__ __align__(16) float HFIN[BATCH * HDIM];                 // final hidden state
__device__ __align__(16) __nv_bfloat16 WIH_H[G4 * DIN];            // W_ih split hi
__device__ __align__(16) __nv_bfloat16 WIH_L[G4 * DIN];            // W_ih split lo (residual)
__device__ __align__(16) float BSUM[G4];                           // b_ih + b_hh

// ---------------- helpers ----------------
__device__ __forceinline__ uint32_t smem_u32(const void* p) {
    uint32_t a;
    asm("{ .reg .u64 t; cvta.to.shared.u64 t, %1; cvt.u32.u64 %0, t; }" : "=r"(a) : "l"(p));
    return a;
}

// ldmatrix x4 (non-transposed), b16
#define LDSM_X4(r, addr) \
    asm volatile("ldmatrix.sync.aligned.m8n8.x4.shared.b16 {%0,%1,%2,%3}, [%4];" \
                 : "=r"((r)[0]), "=r"((r)[1]), "=r"((r)[2]), "=r"((r)[3]) : "r"(addr))

// m16n8k16 bf16 -> fp32 mma (legacy path; works on plain sm_100)
#define MMA_BF16(c, a, b0r, b1r) \
    asm volatile("mma.sync.aligned.m16n8k16.row.col.f32.bf16.bf16.f32 " \
                 "{%0,%1,%2,%3}, {%4,%5,%6,%7}, {%8,%9}, {%0,%1,%2,%3};" \
                 : "+f"((c)[0]), "+f"((c)[1]), "+f"((c)[2]), "+f"((c)[3]) \
                 : "r"((a)[0]), "r"((a)[1]), "r"((a)[2]), "r"((a)[3]), \
                   "r"(b0r), "r"(b1r))

// ---------- math helpers (accurate expf-based) ----------
__device__ __forceinline__ float sigmoid_(float x) { return 1.0f / (1.0f + expf(-x)); }
__device__ __forceinline__ float tanh_(float x)    { return 1.0f - 2.0f / (expf(2.0f * x) + 1.0f); }

// =====================================================================
// Kernel 0: split W_ih into bf16 hi/lo, compute bias sum
// =====================================================================
__global__ __launch_bounds__(256) void wconv(const float* __restrict__ W,
                                             const float* __restrict__ b_ih,
                                             const float* __restrict__ b_hh)
{
    int i = blockIdx.x * 256 + threadIdx.x;
    if (i < G4 * DIN) {
        float v = W[i];
        __nv_bfloat16 h = __float2bfloat16(v);
        WIH_H[i] = h;
        WIH_L[i] = __float2bfloat16(v - __bfloat162float(h));
    }
    if (i < G4) BSUM[i] = b_ih[i] + b_hh[i];
}

// =====================================================================
// Kernel 1: XG = X @ W_ih^T + bias  via mma.sync bf16 split precision
//   M=131072, N=512, K=256. CTA tile 128x128, 256 thr (8 warps, 2x4),
//   warp tile 64x32. K chunks of 64, 3 combos (hh, hl, lh).
//   Smem rows padded to 72 bf16 (144 B) -> conflict-free ldmatrix.
// =====================================================================
#define STR   72                        // bf16 elems per smem row
#define STRB  144                       // bytes per smem row
#define A_HI  0
#define A_LO  18432
#define B_HI  36864
#define B_LO  55296
#define XG_SMEM_TOTAL 73728

__device__ __forceinline__ void split8(const float* f, uint4& hi, uint4& lo) {
    __align__(16) __nv_bfloat162 h[4];
    __align__(16) __nv_bfloat162 l[4];
#pragma unroll
    for (int i = 0; i < 4; i++) {
        float a = f[2 * i], b = f[2 * i + 1];
        __nv_bfloat16 ha = __float2bfloat16(a);
        __nv_bfloat16 hb = __float2bfloat16(b);
        h[i] = __halves2bfloat162(ha, hb);
        l[i] = __halves2bfloat162(__float2bfloat16(a - __bfloat162float(ha)),
                                  __float2bfloat16(b - __bfloat162float(hb)));
    }
    hi = *(const uint4*)h;
    lo = *(const uint4*)l;
}

__global__ __launch_bounds__(256) void xg_mma(const float* __restrict__ X)
{
    extern __shared__ char smem[];
    const uint32_t sb = smem_u32(smem);
    const int tid  = threadIdx.x;
    const int wid  = tid >> 5;
    const int lane = tid & 31;
    const int m0    = blockIdx.x * 128;
    const int n0cta = blockIdx.y * 128;
    const int wm = wid & 1;       // 0..1 -> 64-row block
    const int wn = wid >> 1;      // 0..3 -> 32-col block

    float acc[4][4][4];
#pragma unroll
    for (int i = 0; i < 4; i++)
#pragma unroll
        for (int j = 0; j < 4; j++)
#pragma unroll
            for (int q = 0; q < 4; q++) acc[i][j][q] = 0.0f;

    // ldmatrix lane addressing (A: x4 covers m16 x k16)
    const int lrow = lane & 15;
    const int lkh  = lane >> 4;          // k-half (0: k0-7, 1: k8-15)
    const uint32_t aHiBase = sb + A_HI + (uint32_t)(wm * 64 + lrow) * STRB + lkh * 16;
    const uint32_t aLoBase = aHiBase + (A_LO - A_HI);
    // B: x4 covers 2 n8-tiles x k16
    const int bg   = lane >> 3;
    const int brow = (bg >> 1) * 8 + (lane & 7);
    const int bkh  = bg & 1;
    const uint32_t bHiBase = sb + B_HI + (uint32_t)(wn * 32 + brow) * STRB + bkh * 16;
    const uint32_t bLoBase = bHiBase + (B_LO - B_HI);

    // loader identity: 2 threads per row, 32 k-elems each
    const int lr = tid >> 1;
    const int lk = (tid & 1) * 32;

    for (int kc = 0; kc < 4; kc++) {
        // ---- stage A chunk [128 x 64] fp32 -> bf16 hi/lo ----
        const float* xrow = X + (size_t)(m0 + lr) * DIN + kc * 64 + lk;
#pragma unroll
        for (int j = 0; j < 4; j++) {
            __align__(16) float f[8];
            *(float4*)(f)     = *(const float4*)(xrow + j * 8);
            *(float4*)(f + 4) = *(const float4*)(xrow + j * 8 + 4);
            uint4 hv, lv;
            split8(f, hv, lv);
            uint32_t off = (uint32_t)lr * STRB + (uint32_t)(lk + j * 8) * 2;
            *(uint4*)(smem + A_HI + off) = hv;
            *(uint4*)(smem + A_LO + off) = lv;
        }
        // ---- stage B chunk [128 x 64] (already bf16 hi/lo in global) ----
        {
            const __nv_bfloat16* wh = WIH_H + (size_t)(n0cta + lr) * DIN + kc * 64 + lk;
            const __nv_bfloat16* wl = WIH_L + (size_t)(n0cta + lr) * DIN + kc * 64 + lk;
#pragma unroll
            for (int j = 0; j < 4; j++) {
                uint4 hv = *(const uint4*)(wh + j * 8);
                uint4 lv = *(const uint4*)(wl + j * 8);
                uint32_t off = (uint32_t)lr * STRB + (uint32_t)(lk + j * 8) * 2;
                *(uint4*)(smem + B_HI + off) = hv;
                *(uint4*)(smem + B_LO + off) = lv;
            }
        }
        __syncthreads();

        // ---- compute: 4 k16 steps ----
#pragma unroll
        for (int ks = 0; ks < 4; ks++) {
            uint32_t ah[16], al[16];
#pragma unroll
            for (int i = 0; i < 4; i++) {
                LDSM_X4(ah + 4 * i, aHiBase + (uint32_t)i * 16 * STRB + ks * 32);
                LDSM_X4(al + 4 * i, aLoBase + (uint32_t)i * 16 * STRB + ks * 32);
            }
#pragma unroll
            for (int jp = 0; jp < 2; jp++) {
                uint32_t bh[4], bl[4];
                LDSM_X4(bh, bHiBase + (uint32_t)jp * 16 * STRB + ks * 32);
                LDSM_X4(bl, bLoBase + (uint32_t)jp * 16 * STRB + ks * 32);
#pragma unroll
                for (int i = 0; i < 4; i++) {
#pragma unroll
                    for (int jj = 0; jj < 2; jj++) {
                        const int j = jp * 2 + jj;
                        MMA_BF16(acc[i][j], ah + 4 * i, bh[2 * jj], bh[2 * jj + 1]);
                        MMA_BF16(acc[i][j], ah + 4 * i, bl[2 * jj], bl[2 * jj + 1]);
                        MMA_BF16(acc[i][j], al + 4 * i, bh[2 * jj], bh[2 * jj + 1]);
                    }
                }
            }
        }
        __syncthreads();
    }

    // ---- epilogue: add bias, store ----
    const int group = lane >> 2;
    const int qc    = (lane & 3) * 2;
    float bias[4][2];
#pragma unroll
    for (int j = 0; j < 4; j++) {
        int n = n0cta + wn * 32 + 8 * j + qc;
        bias[j][0] = BSUM[n];
        bias[j][1] = BSUM[n + 1];
    }
#pragma unroll
    for (int i = 0; i < 4; i++) {
#pragma unroll
        for (int h = 0; h < 2; h++) {
            const int row = m0 + wm * 64 + 16 * i + group + 8 * h;
            float* orow = XG + (size_t)row * G4 + n0cta + wn * 32;
#pragma unroll
            for (int j = 0; j < 4; j++) {
                float2 v;
                v.x = acc[i][j][2 * h]     + bias[j][0];
                v.y = acc[i][j][2 * h + 1] + bias[j][1];
                *(float2*)(orow + 8 * j + qc) = v;
            }
        }
    }
}

// =====================================================================
// Kernel 2: recurrence (round-1 version, known good, ~990us)
// =====================================================================
__global__ void __cluster_dims__(2, 1, 1) __launch_bounds__(256)
lstm_rec(const float* __restrict__ h0,
         const float* __restrict__ c0,
         const float* __restrict__ W_hh)
{
    extern __shared__ float sm[];
    float* Wsm = sm;                     // [128][256]  (k-major)   32768 floats
    float* hsT = sm + 32768;             // [2][128][4]              1024 floats
    float* Gsm = sm + 32768 + 1024;      // [4 kc][4 b][256 j]       4096 floats

    const int tid  = threadIdx.x;
    const int r    = blockIdx.x & 1;
    const int pair = blockIdx.x >> 1;
    const int b0   = pair * 4;
    const int peer = r ^ 1;

    {
        const int j = tid;
        const int gate = j >> 6;
        const int col  = j & 63;
        const int jg = gate * 128 + r * 64 + col;
        const float4* wrow = (const float4*)(W_hh + (size_t)jg * HDIM);
#pragma unroll
        for (int kk = 0; kk < 32; kk++) {
            float4 v = wrow[kk];
            int k = kk * 4;
            Wsm[(k + 0) * 256 + j] = v.x;
            Wsm[(k + 1) * 256 + j] = v.y;
            Wsm[(k + 2) * 256 + j] = v.z;
            Wsm[(k + 3) * 256 + j] = v.w;
        }
    }
    for (int idx = tid; idx < 512; idx += 256) {
        int b = idx & 3, k = idx >> 2;
        hsT[k * 4 + b] = h0[(size_t)(b0 + b) * HDIM + k];
    }

    const int ab   = tid >> 6;
    const int acol = tid & 63;
    const int kcol = r * 64 + acol;
    float cst = c0[(size_t)(b0 + ab) * HDIM + kcol];
    float hout = 0.0f;

    const int kc = tid >> 6;
    const int g  = tid & 63;

    const uint32_t hsT_u32 = smem_u32(hsT);

    __syncthreads();

    const float* xg_base = XG + (size_t)(b0 + ab) * G4 + kcol;

    for (int t = 0; t < T_STEPS; t++) {
        const int pbuf = t & 1;
        const int nbuf = pbuf ^ 1;

        const float* xg = xg_base + (size_t)t * BATCH * G4;
        float xgv0 = xg[0];
        float xgv1 = xg[128];
        float xgv2 = xg[256];
        float xgv3 = xg[384];

        float4 a0 = {0.f, 0.f, 0.f, 0.f}, a1 = a0, a2 = a0, a3 = a0;
        const float* hbase = hsT + pbuf * 512 + kc * 32 * 4;
        const float* wbase = Wsm + kc * 32 * 256 + 4 * g;
#pragma unroll
        for (int kk = 0; kk < 32; kk++) {
            float4 w = *(const float4*)(wbase + kk * 256);
            float4 h = *(const float4*)(hbase + kk * 4);
            a0.x += w.x * h.x; a0.y += w.y * h.x; a0.z += w.z * h.x; a0.w += w.w * h.x;
            a1.x += w.x * h.y; a1.y += w.y * h.y; a1.z += w.z * h.y; a1.w += w.w * h.y;
            a2.x += w.x * h.z; a2.y += w.y * h.z; a2.z += w.z * h.z; a2.w += w.w * h.z;
            a3.x += w.x * h.w; a3.y += w.y * h.w; a3.z += w.z * h.w; a3.w += w.w * h.w;
        }
        ((float4*)(Gsm + kc * 1024 + 0 * 256))[g] = a0;
        ((float4*)(Gsm + kc * 1024 + 1 * 256))[g] = a1;
        ((float4*)(Gsm + kc * 1024 + 2 * 256))[g] = a2;
        ((float4*)(Gsm + kc * 1024 + 3 * 256))[g] = a3;

        __syncthreads();

        const float* Gb = Gsm + ab * 256;
        float p0 = xgv0 + Gb[0 * 1024 + acol]        + Gb[1 * 1024 + acol]        + Gb[2 * 1024 + acol]        + Gb[3 * 1024 + acol];
        float p1 = xgv1 + Gb[0 * 1024 + 64 + acol]   + Gb[1 * 1024 + 64 + acol]   + Gb[2 * 1024 + 64 + acol]   + Gb[3 * 1024 + 64 + acol];
        float p2 = xgv2 + Gb[0 * 1024 + 128 + acol]  + Gb[1 * 1024 + 128 + acol]  + Gb[2 * 1024 + 128 + acol]  + Gb[3 * 1024 + 128 + acol];
        float p3 = xgv3 + Gb[0 * 1024 + 192 + acol]  + Gb[1 * 1024 + 192 + acol]  + Gb[2 * 1024 + 192 + acol]  + Gb[3 * 1024 + 192 + acol];

        float ig = sigmoid_(p0);
        float fg = sigmoid_(p1);
        float gg = tanh_(p2);
        float og = sigmoid_(p3);
        cst  = fg * cst + ig * gg;
        hout = og * tanh_(cst);

        const int off = nbuf * 512 + kcol * 4 + ab;
        hsT[off] = hout;
        uint32_t rem;
        asm volatile("mapa.shared::cluster.u32 %0, %1, %2;"
                     : "=r"(rem) : "r"(hsT_u32 + off * 4), "r"(peer));
        asm volatile("st.shared::cluster.f32 [%0], %1;" :: "r"(rem), "f"(hout) : "memory");

        asm volatile("barrier.cluster.arrive.aligned;" ::: "memory");
        asm volatile("barrier.cluster.wait.aligned;" ::: "memory");
    }

    HFIN[(size_t)(b0 + ab) * HDIM + kcol] = hout;
}

// =====================================================================
// Kernel 3: out[b] = HFIN[b,:] . fc_w + fc_b
// =====================================================================
__global__ __launch_bounds__(256) void fc_head(const float* __restrict__ fcw,
                                               const float* __restrict__ fcb,
                                               float* __restrict__ out)
{
    const int b = threadIdx.x;
    const float4* hr = (const float4*)(HFIN + (size_t)b * HDIM);
    const float4* w4 = (const float4*)fcw;
    float s = 0.0f;
#pragma unroll
    for (int k = 0; k < HDIM / 4; k++) {
        float4 h = hr[k];
        float4 w = w4[k];
        s += h.x * w.x + h.y * w.y + h.z * w.z + h.w * w.w;
    }
    out[b] = s + fcb[0];
}

// =====================================================================
extern "C" void kernel_launch(void* const* d_in, const int* in_sizes, int n_in,
                              void* d_out, int out_size)
{
    const float* x    = (const float*)d_in[0];
    const float* h0   = (const float*)d_in[1];
    const float* c0   = (const float*)d_in[2];
    const float* W_ih = (const float*)d_in[3];
    const float* W_hh = (const float*)d_in[4];
    const float* b_ih = (const float*)d_in[5];
    const float* b_hh = (const float*)d_in[6];
    const float* fc_w = (const float*)d_in[7];
    const float* fc_b = (const float*)d_in[8];
    float* out = (float*)d_out;

    (void)in_sizes; (void)n_in; (void)out_size;

    // 0) split W_ih to bf16 hi/lo + bias sum
    wconv<<<512, 256>>>(W_ih, b_ih, b_hh);

    // 1) input-projection GEMM on tensor cores (mma.sync bf16 split precision)
    cudaFuncSetAttribute(xg_mma, cudaFuncAttributeMaxDynamicSharedMemorySize, XG_SMEM_TOTAL);
    xg_mma<<<dim3(1024, 4), 256, XG_SMEM_TOTAL>>>(x);

    // 2) recurrence: 64 cluster-pairs x 2 CTAs
    const int rec_smem = (32768 + 1024 + 4096) * (int)sizeof(float);
    cudaFuncSetAttribute(lstm_rec, cudaFuncAttributeMaxDynamicSharedMemorySize, rec_smem);
    lstm_rec<<<128, 256, rec_smem>>>(h0, c0, W_hh);

    // 3) FC head
    fc_head<<<1, 256>>>(fc_w, fc_b, out);
}